// round 12
// baseline (speedup 1.0000x reference)
#include <cuda_runtime.h>
#include <cuda_bf16.h>
#include <stdint.h>

#define N_ROWS 1024   // N
#define P_PIX  1024   // P
#define E_DIM  512    // ENC / TAG / LANG
#define A_DIM  256    // ATT

// fp32 scratch
__device__ float g_att1 [P_PIX * A_DIM];    // (P, A)  enc@We^T + be
__device__ float g_att23[N_ROWS * A_DIM];   // (N, A)  dh@Wt^T + bt
__device__ float g_att3 [N_ROWS * A_DIM];   // (N, A)  lo@Wl^T + bl
__device__ float g_att  [N_ROWS * P_PIX];   // (N, P)

// pre-split packed scratch: uint2 = {bf16x2 hi (k even,k odd), bf16x2 lo}
__device__ uint2 g_encA [P_PIX  * E_DIM / 2];   // [p][e/2]
__device__ uint2 g_dhA  [N_ROWS * E_DIM / 2];   // [n][e/2]
__device__ uint2 g_loA  [N_ROWS * E_DIM / 2];   // [n][e/2]
__device__ uint2 g_WeP  [A_DIM  * E_DIM / 2];   // [a][e/2]
__device__ uint2 g_WtP  [A_DIM  * E_DIM / 2];
__device__ uint2 g_WlP  [A_DIM  * E_DIM / 2];
__device__ uint2 g_encB [(P_PIX / 2) * E_DIM];  // [p/2][e]
__device__ uint2 g_alphaP[N_ROWS * P_PIX / 2];  // [n][p/2]

// ---- bf16 helpers ----
__device__ __forceinline__ uint32_t pack_bf16(__nv_bfloat16 a, __nv_bfloat16 b) {
    __nv_bfloat162 t; t.x = a; t.y = b;
    return *(uint32_t*)&t;
}
__device__ __forceinline__ uint2 split2(float x0, float x1) {
    __nv_bfloat16 h0 = __float2bfloat16_rn(x0);
    __nv_bfloat16 h1 = __float2bfloat16_rn(x1);
    float r0 = x0 - __bfloat162float(h0);
    float r1 = x1 - __bfloat162float(h1);
    uint2 o;
    o.x = pack_bf16(h0, h1);
    o.y = pack_bf16(__float2bfloat16_rn(r0), __float2bfloat16_rn(r1));
    return o;
}

#define MMA_BF16(d, a, b)                                                   \
  asm("mma.sync.aligned.m16n8k16.row.col.f32.bf16.bf16.f32 "                \
      "{%0,%1,%2,%3},{%4,%5,%6,%7},{%8,%9},{%0,%1,%2,%3};"                  \
      : "+f"(d[0]), "+f"(d[1]), "+f"(d[2]), "+f"(d[3])                      \
      : "r"(a[0]), "r"(a[1]), "r"(a[2]), "r"(a[3]), "r"(b[0]), "r"(b[1]))

__device__ __forceinline__ void cpa16(void* dst, const void* src) {
    uint32_t d = (uint32_t)__cvta_generic_to_shared(dst);
    asm volatile("cp.async.cg.shared.global [%0], [%1], 16;" :: "r"(d), "l"(src));
}
#define CP_COMMIT  asm volatile("cp.async.commit_group;")
#define CP_WAIT(n) asm volatile("cp.async.wait_group %0;" :: "n"(n))

#define SPAD 20   // uint2 row stride: 40 words = 8 mod 32 -> conflict-free

// ---------------------------------------------------------------------------
// Kernel 0: presplit v2 — 4 floats per thread.
//   z=0..2: enc/dh/lo ; z=3..5: We/Wt/Wl ; z=6: encB (pairs across rows)
// ---------------------------------------------------------------------------
__global__ __launch_bounds__(256)
void presplit_kernel(const float* __restrict__ enc, const float* __restrict__ dh,
                     const float* __restrict__ lo,  const float* __restrict__ We,
                     const float* __restrict__ Wt,  const float* __restrict__ Wl)
{
    const int z   = blockIdx.z;
    const int idx = blockIdx.x * 256 + threadIdx.x;
    if (z < 6) {
        const float* X; uint2* Y; int count4;
        switch (z) {
            case 0: X = enc; Y = g_encA; count4 = P_PIX  * E_DIM / 4; break;
            case 1: X = dh;  Y = g_dhA;  count4 = N_ROWS * E_DIM / 4; break;
            case 2: X = lo;  Y = g_loA;  count4 = N_ROWS * E_DIM / 4; break;
            case 3: X = We;  Y = g_WeP;  count4 = A_DIM  * E_DIM / 4; break;
            case 4: X = Wt;  Y = g_WtP;  count4 = A_DIM  * E_DIM / 4; break;
            default:X = Wl;  Y = g_WlP;  count4 = A_DIM  * E_DIM / 4; break;
        }
        if (idx < count4) {
            float4 v = *(const float4*)&X[4 * idx];
            uint2 u0 = split2(v.x, v.y);
            uint2 u1 = split2(v.z, v.w);
            uint4 pk; pk.x = u0.x; pk.y = u0.y; pk.z = u1.x; pk.w = u1.y;
            *(uint4*)&Y[2 * idx] = pk;
        }
    } else {
        // encB: pair rows (2*p2, 2*p2+1), 2 columns per thread
        if (idx < (P_PIX / 2) * (E_DIM / 2)) {
            int p2 = idx / (E_DIM / 2);
            int ec = (idx % (E_DIM / 2)) * 2;
            float2 r0 = *(const float2*)&enc[(2 * p2) * E_DIM + ec];
            float2 r1 = *(const float2*)&enc[(2 * p2 + 1) * E_DIM + ec];
            uint2 u0 = split2(r0.x, r1.x);
            uint2 u1 = split2(r0.y, r1.y);
            uint4 pk; pk.x = u0.x; pk.y = u0.y; pk.z = u1.x; pk.w = u1.y;
            *(uint4*)&g_encB[p2 * E_DIM + ec] = pk;
        }
    }
}

// ---------------------------------------------------------------------------
// Kernel 1: tc_attproj — C = A @ W^T + bias (M=1024, N=256, K=512), per z.
// CTA tile 64m x 32n, 128 threads (4 warps, warp tile 32x16), bf16 3-split.
// ---------------------------------------------------------------------------
__global__ __launch_bounds__(128)
void tc_attproj(const float* __restrict__ be, const float* __restrict__ bt,
                const float* __restrict__ bl)
{
    __shared__ uint2 Apk[2][64][SPAD];
    __shared__ uint2 Bpk[2][32][SPAD];

    const int z = blockIdx.z;
    const uint2* Asrc = (z == 0) ? g_encA : (z == 1) ? g_dhA : g_loA;
    const uint2* Bsrc = (z == 0) ? g_WeP  : (z == 1) ? g_WtP : g_WlP;
    const float* bv   = (z == 0) ? be     : (z == 1) ? bt    : bl;
    float*       C    = (z == 0) ? g_att1 : (z == 1) ? g_att23 : g_att3;

    const int tid = threadIdx.x;
    const int m0  = blockIdx.y * 64;
    const int n0  = blockIdx.x * 32;

    const int lane = tid & 31, wid = tid >> 5;
    const int wm = (wid & 1) * 32;
    const int wn = (wid >> 1) * 16;
    const int g = lane >> 2, t = lane & 3;

    float acc[2][2][4] = {};

    const int KP_ROW = E_DIM / 2;

    #define STAGE_P(kt, b)                                                   \
    {                                                                        \
        int kpb = (kt) * 16;                                                 \
        _Pragma("unroll")                                                    \
        for (int j = 0; j < 4; j++) {                                        \
            int o = tid + 128 * j;                                           \
            int r = o >> 3, kpc = (o & 7) * 2;                               \
            cpa16(&Apk[b][r][kpc], Asrc + (m0 + r) * KP_ROW + kpb + kpc);    \
        }                                                                    \
        _Pragma("unroll")                                                    \
        for (int j = 0; j < 2; j++) {                                        \
            int o = tid + 128 * j;                                           \
            int r = o >> 3, kpc = (o & 7) * 2;                               \
            cpa16(&Bpk[b][r][kpc], Bsrc + (n0 + r) * KP_ROW + kpb + kpc);    \
        }                                                                    \
        CP_COMMIT;                                                           \
    }

    STAGE_P(0, 0);
    const int T = E_DIM / 32;
    for (int it = 0; it < T; it++) {
        const int b = it & 1;
        if (it + 1 < T) { STAGE_P(it + 1, (it + 1) & 1); CP_WAIT(1); }
        else           { CP_WAIT(0); }
        __syncthreads();

        #pragma unroll
        for (int ks = 0; ks < 2; ks++) {
            const int kp0 = ks * 8;
            uint32_t Ah[2][4], Al[2][4];
            #pragma unroll
            for (int mf = 0; mf < 2; mf++) {
                int r = wm + mf * 16 + g;
                uint2 p00 = Apk[b][r][kp0 + t];
                uint2 p10 = Apk[b][r + 8][kp0 + t];
                uint2 p01 = Apk[b][r][kp0 + t + 4];
                uint2 p11 = Apk[b][r + 8][kp0 + t + 4];
                Ah[mf][0] = p00.x; Ah[mf][1] = p10.x; Ah[mf][2] = p01.x; Ah[mf][3] = p11.x;
                Al[mf][0] = p00.y; Al[mf][1] = p10.y; Al[mf][2] = p01.y; Al[mf][3] = p11.y;
            }
            uint32_t Bh[2][2], Bl[2][2];
            #pragma unroll
            for (int nf = 0; nf < 2; nf++) {
                int c = wn + nf * 8 + g;
                uint2 q0 = Bpk[b][c][kp0 + t];
                uint2 q1 = Bpk[b][c][kp0 + t + 4];
                Bh[nf][0] = q0.x; Bh[nf][1] = q1.x;
                Bl[nf][0] = q0.y; Bl[nf][1] = q1.y;
            }
            #pragma unroll
            for (int mf = 0; mf < 2; mf++)
                #pragma unroll
                for (int nf = 0; nf < 2; nf++) {
                    MMA_BF16(acc[mf][nf], Ah[mf], Bh[nf]);
                    MMA_BF16(acc[mf][nf], Ah[mf], Bl[nf]);
                    MMA_BF16(acc[mf][nf], Al[mf], Bh[nf]);
                }
        }
        __syncthreads();
    }
    #undef STAGE_P

    #pragma unroll
    for (int mf = 0; mf < 2; mf++)
        #pragma unroll
        for (int nf = 0; nf < 2; nf++) {
            int r = m0 + wm + mf * 16 + g;
            int c = n0 + wn + nf * 8 + t * 2;
            float b0 = bv[c], b1 = bv[c + 1];
            *(float2*)&C[r * A_DIM + c] =
                make_float2(acc[mf][nf][0] + b0, acc[mf][nf][1] + b1);
            *(float2*)&C[(r + 8) * A_DIM + c] =
                make_float2(acc[mf][nf][2] + b0, acc[mf][nf][3] + b1);
        }
}

// ---------------------------------------------------------------------------
// Kernel 2: att_main v4 — att[n,p] = sum_a relu(att1[p,a]+att23[n,a]+att3[n,a])*Wf[a]
// CA=32, register double-buffered staging, one sync per chunk.
// ---------------------------------------------------------------------------
#define CA2 32
__global__ __launch_bounds__(256)
void att_main_v4(const float* __restrict__ Wf)
{
    __shared__ float s1 [2][CA2][68];   // [buf][a][p]
    __shared__ float s23[2][CA2][68];   // [buf][a][n]
    __shared__ float sw[A_DIM];

    const int tid = threadIdx.x;
    const int tx  = tid & 15;           // p micro (4)
    const int ty  = tid >> 4;           // n micro (4)
    const int p0  = blockIdx.x * 64;
    const int n0  = blockIdx.y * 64;

    sw[tid] = Wf[tid];                  // 256 threads, A_DIM=256

    const int la = tid & 31;            // a within chunk
    const int lq = tid >> 5;            // 0..7

    float acc[4][4] = {};

    // prologue: load + store chunk 0
    {
        float f1[8], f2[8];
        #pragma unroll
        for (int i = 0; i < 8; i++) {
            int r = lq + 8 * i;
            f1[i] = g_att1 [(p0 + r) * A_DIM + la];
            f2[i] = g_att23[(n0 + r) * A_DIM + la]
                  + g_att3 [(n0 + r) * A_DIM + la];
        }
        #pragma unroll
        for (int i = 0; i < 8; i++) {
            int r = lq + 8 * i;
            s1 [0][la][r] = f1[i];
            s23[0][la][r] = f2[i];
        }
    }
    __syncthreads();

    const int NCH = A_DIM / CA2;        // 8
    for (int c = 0; c < NCH; c++) {
        const int b = c & 1;
        float f1[8], f2[8];
        if (c + 1 < NCH) {
            const int a0 = (c + 1) * CA2;
            #pragma unroll
            for (int i = 0; i < 8; i++) {
                int r = lq + 8 * i;
                f1[i] = g_att1 [(p0 + r) * A_DIM + a0 + la];
                f2[i] = g_att23[(n0 + r) * A_DIM + a0 + la]
                      + g_att3 [(n0 + r) * A_DIM + a0 + la];
            }
        }

        const int ab = c * CA2;
        #pragma unroll 4
        for (int a = 0; a < CA2; a++) {
            float wa = sw[ab + a];
            float4 r1 = *(const float4*)&s1 [b][a][tx * 4];
            float4 r2 = *(const float4*)&s23[b][a][ty * 4];
            float x1[4] = {r1.x, r1.y, r1.z, r1.w};
            float x2[4] = {r2.x, r2.y, r2.z, r2.w};
            #pragma unroll
            for (int j = 0; j < 4; j++)
                #pragma unroll
                for (int i = 0; i < 4; i++)
                    acc[j][i] += fmaxf(x1[i] + x2[j], 0.0f) * wa;
        }

        if (c + 1 < NCH) {
            #pragma unroll
            for (int i = 0; i < 8; i++) {
                int r = lq + 8 * i;
                s1 [b ^ 1][la][r] = f1[i];
                s23[b ^ 1][la][r] = f2[i];
            }
            __syncthreads();
        }
    }

    #pragma unroll
    for (int j = 0; j < 4; j++) {
        float4 o = make_float4(acc[j][0], acc[j][1], acc[j][2], acc[j][3]);
        *(float4*)&g_att[(n0 + ty * 4 + j) * P_PIX + p0 + tx * 4] = o;
    }
}

// ---------------------------------------------------------------------------
// Kernel 3: softmax v2 — one warp per row, zero block syncs.
// 8 rows per 256-thread block, grid = 128.
// ---------------------------------------------------------------------------
__global__ __launch_bounds__(256)
void softmax_v2(float* __restrict__ alpha)
{
    const int tid  = threadIdx.x;
    const int lane = tid & 31;
    const int w    = tid >> 5;
    const int n    = blockIdx.x * 8 + w;

    const float4* row = (const float4*)(g_att + n * P_PIX);

    float4 v[8];
    #pragma unroll
    for (int j = 0; j < 8; j++) v[j] = row[lane + 32 * j];

    float m = -1e30f;
    #pragma unroll
    for (int j = 0; j < 8; j++)
        m = fmaxf(m, fmaxf(fmaxf(v[j].x, v[j].y), fmaxf(v[j].z, v[j].w)));
    #pragma unroll
    for (int o = 16; o > 0; o >>= 1) m = fmaxf(m, __shfl_xor_sync(0xffffffffu, m, o));

    float s = 0.0f;
    #pragma unroll
    for (int j = 0; j < 8; j++) {
        v[j].x = __expf(v[j].x - m); s += v[j].x;
        v[j].y = __expf(v[j].y - m); s += v[j].y;
        v[j].z = __expf(v[j].z - m); s += v[j].z;
        v[j].w = __expf(v[j].w - m); s += v[j].w;
    }
    #pragma unroll
    for (int o = 16; o > 0; o >>= 1) s += __shfl_xor_sync(0xffffffffu, s, o);
    const float inv = 1.0f / s;

    float4* arow = (float4*)(alpha + n * P_PIX);
    uint4*  prow = (uint4*)(g_alphaP + n * (P_PIX / 2));
    #pragma unroll
    for (int j = 0; j < 8; j++) {
        float a0 = v[j].x * inv, a1 = v[j].y * inv;
        float a2 = v[j].z * inv, a3 = v[j].w * inv;
        arow[lane + 32 * j] = make_float4(a0, a1, a2, a3);
        uint2 u0 = split2(a0, a1);
        uint2 u1 = split2(a2, a3);
        uint4 pk; pk.x = u0.x; pk.y = u0.y; pk.z = u1.x; pk.w = u1.y;
        prow[lane + 32 * j] = pk;
    }
}

// ---------------------------------------------------------------------------
// Kernel 4: tc_gemm_ab — awe = alpha @ enc  (M=1024, N=512, K=1024)
// CTA tile 64m x 32n, 128 threads (4 warps, warp tile 32x16), bf16 3-split.
// ---------------------------------------------------------------------------
__global__ __launch_bounds__(128)
void tc_gemm_ab(float* __restrict__ C)
{
    __shared__ uint2 Apk[2][64][SPAD];
    __shared__ uint2 Bpk[2][16][36];

    const int tid = threadIdx.x;
    const int m0  = blockIdx.y * 64;
    const int n0  = blockIdx.x * 32;

    const int lane = tid & 31, wid = tid >> 5;
    const int wm = (wid & 1) * 32;
    const int wn = (wid >> 1) * 16;
    const int g = lane >> 2, t = lane & 3;

    float acc[2][2][4] = {};

    #define STAGE_G(kt, b)                                                    \
    {                                                                         \
        int kpb = (kt) * 16;                                                  \
        _Pragma("unroll")                                                     \
        for (int j = 0; j < 4; j++) {                                         \
            int o = tid + 128 * j;                                            \
            int r = o >> 3, kpc = (o & 7) * 2;                                \
            cpa16(&Apk[b][r][kpc],                                            \
                  g_alphaP + (m0 + r) * (P_PIX / 2) + kpb + kpc);             \
        }                                                                     \
        _Pragma("unroll")                                                     \
        for (int j = 0; j < 2; j++) {                                         \
            int o = tid + 128 * j;                                            \
            int kp = o >> 4, nc = (o & 15) * 2;                               \
            cpa16(&Bpk[b][kp][nc], g_encB + (kpb + kp) * E_DIM + n0 + nc);    \
        }                                                                     \
        CP_COMMIT;                                                            \
    }

    STAGE_G(0, 0);
    const int T = P_PIX / 32;
    for (int it = 0; it < T; it++) {
        const int b = it & 1;
        if (it + 1 < T) { STAGE_G(it + 1, (it + 1) & 1); CP_WAIT(1); }
        else           { CP_WAIT(0); }
        __syncthreads();

        #pragma unroll
        for (int ks = 0; ks < 2; ks++) {
            const int kp0 = ks * 8;
            uint32_t Ah[2][4], Al[2][4];
            #pragma unroll
            for (int mf = 0; mf < 2; mf++) {
                int r = wm + mf * 16 + g;
                uint2 p00 = Apk[b][r][kp0 + t];
                uint2 p10 = Apk[b][r + 8][kp0 + t];
                uint2 p01 = Apk[b][r][kp0 + t + 4];
                uint2 p11 = Apk[b][r + 8][kp0 + t + 4];
                Ah[mf][0] = p00.x; Ah[mf][1] = p10.x; Ah[mf][2] = p01.x; Ah[mf][3] = p11.x;
                Al[mf][0] = p00.y; Al[mf][1] = p10.y; Al[mf][2] = p01.y; Al[mf][3] = p11.y;
            }
            uint32_t Bh[2][2], Bl[2][2];
            #pragma unroll
            for (int nf = 0; nf < 2; nf++) {
                int c = wn + nf * 8 + g;
                uint2 q0 = Bpk[b][kp0 + t][c];
                uint2 q1 = Bpk[b][kp0 + t + 4][c];
                Bh[nf][0] = q0.x; Bh[nf][1] = q1.x;
                Bl[nf][0] = q0.y; Bl[nf][1] = q1.y;
            }
            #pragma unroll
            for (int mf = 0; mf < 2; mf++)
                #pragma unroll
                for (int nf = 0; nf < 2; nf++) {
                    MMA_BF16(acc[mf][nf], Ah[mf], Bh[nf]);
                    MMA_BF16(acc[mf][nf], Ah[mf], Bl[nf]);
                    MMA_BF16(acc[mf][nf], Al[mf], Bh[nf]);
                }
        }
        __syncthreads();
    }
    #undef STAGE_G

    #pragma unroll
    for (int mf = 0; mf < 2; mf++)
        #pragma unroll
        for (int nf = 0; nf < 2; nf++) {
            int r = m0 + wm + mf * 16 + g;
            int c = n0 + wn + nf * 8 + t * 2;
            *(float2*)&C[r * E_DIM + c] =
                make_float2(acc[mf][nf][0], acc[mf][nf][1]);
            *(float2*)&C[(r + 8) * E_DIM + c] =
                make_float2(acc[mf][nf][2], acc[mf][nf][3]);
        }
}

// ---------------------------------------------------------------------------
// Launch
// ---------------------------------------------------------------------------
extern "C" void kernel_launch(void* const* d_in, const int* in_sizes, int n_in,
                              void* d_out, int out_size)
{
    (void)in_sizes; (void)n_in; (void)out_size;
    const float* enc = (const float*)d_in[0];
    const float* dh  = (const float*)d_in[1];
    const float* lo  = (const float*)d_in[2];
    const float* We  = (const float*)d_in[3];
    const float* be  = (const float*)d_in[4];
    const float* Wt  = (const float*)d_in[5];
    const float* bt  = (const float*)d_in[6];
    const float* Wl  = (const float*)d_in[7];
    const float* bl  = (const float*)d_in[8];
    const float* Wf  = (const float*)d_in[9];
    // d_in[10] = bf: uniform shift, cancels in softmax.

    float* awe   = (float*)d_out;
    float* alpha = (float*)d_out + N_ROWS * E_DIM;

    dim3 g0(512, 1, 7);
    presplit_kernel<<<g0, 256>>>(enc, dh, lo, We, Wt, Wl);

    dim3 g1(A_DIM / 32, 1024 / 64, 3);
    tc_attproj<<<g1, 128>>>(be, bt, bl);

    dim3 g2(P_PIX / 64, N_ROWS / 64);
    att_main_v4<<<g2, 256>>>(Wf);

    softmax_v2<<<N_ROWS / 8, 256>>>(alpha);

    dim3 g4(E_DIM / 32, N_ROWS / 64);
    tc_gemm_ab<<<g4, 128>>>(awe);
}

// round 13
// speedup vs baseline: 1.0280x; 1.0280x over previous
#include <cuda_runtime.h>
#include <cuda_bf16.h>
#include <stdint.h>

typedef unsigned long long ull;

#define N_ROWS 1024   // N
#define P_PIX  1024   // P
#define E_DIM  512    // ENC / TAG / LANG
#define A_DIM  256    // ATT

// fp32 scratch
__device__ float g_att1 [P_PIX * A_DIM];    // (P, A)  enc@We^T + be
__device__ float g_att23[N_ROWS * A_DIM];   // (N, A)  dh@Wt^T + bt
__device__ float g_att3 [N_ROWS * A_DIM];   // (N, A)  lo@Wl^T + bl
__device__ float g_att  [N_ROWS * P_PIX];   // (N, P)

// pre-split packed scratch: uint2 = {bf16x2 hi (k even,k odd), bf16x2 lo}
__device__ uint2 g_encA [P_PIX  * E_DIM / 2];   // [p][e/2]
__device__ uint2 g_dhA  [N_ROWS * E_DIM / 2];   // [n][e/2]
__device__ uint2 g_loA  [N_ROWS * E_DIM / 2];   // [n][e/2]
__device__ uint2 g_WeP  [A_DIM  * E_DIM / 2];   // [a][e/2]
__device__ uint2 g_WtP  [A_DIM  * E_DIM / 2];
__device__ uint2 g_WlP  [A_DIM  * E_DIM / 2];
__device__ uint2 g_encB [(P_PIX / 2) * E_DIM];  // [p/2][e]
__device__ uint2 g_alphaP[N_ROWS * P_PIX / 2];  // [n][p/2]

// ---- bf16 helpers ----
__device__ __forceinline__ uint32_t pack_bf16(__nv_bfloat16 a, __nv_bfloat16 b) {
    __nv_bfloat162 t; t.x = a; t.y = b;
    return *(uint32_t*)&t;
}
__device__ __forceinline__ uint2 split2(float x0, float x1) {
    __nv_bfloat16 h0 = __float2bfloat16_rn(x0);
    __nv_bfloat16 h1 = __float2bfloat16_rn(x1);
    float r0 = x0 - __bfloat162float(h0);
    float r1 = x1 - __bfloat162float(h1);
    uint2 o;
    o.x = pack_bf16(h0, h1);
    o.y = pack_bf16(__float2bfloat16_rn(r0), __float2bfloat16_rn(r1));
    return o;
}

#define MMA_BF16(d, a, b)                                                   \
  asm("mma.sync.aligned.m16n8k16.row.col.f32.bf16.bf16.f32 "                \
      "{%0,%1,%2,%3},{%4,%5,%6,%7},{%8,%9},{%0,%1,%2,%3};"                  \
      : "+f"(d[0]), "+f"(d[1]), "+f"(d[2]), "+f"(d[3])                      \
      : "r"(a[0]), "r"(a[1]), "r"(a[2]), "r"(a[3]), "r"(b[0]), "r"(b[1]))

__device__ __forceinline__ void cpa16(void* dst, const void* src) {
    uint32_t d = (uint32_t)__cvta_generic_to_shared(dst);
    asm volatile("cp.async.cg.shared.global [%0], [%1], 16;" :: "r"(d), "l"(src));
}
#define CP_COMMIT  asm volatile("cp.async.commit_group;")
#define CP_WAIT(n) asm volatile("cp.async.wait_group %0;" :: "n"(n))

#define SPAD 20   // uint2 row stride: 40 words = 8 mod 32 -> conflict-free

// ---- packed relu-dot: acc += max(x1+x2, 0) * w, relu on halves in C++ ----
__device__ __forceinline__ void relu_fma2(ull& acc, ull x1, ull x2, ull w)
{
    ull t;
    asm("add.rn.f32x2 %0, %1, %2;" : "=l"(t) : "l"(x1), "l"(x2));
    float lo = fmaxf(__uint_as_float((unsigned)t), 0.0f);
    float hi = fmaxf(__uint_as_float((unsigned)(t >> 32)), 0.0f);
    ull r;
    asm("mov.b64 %0, {%1, %2};" : "=l"(r) : "f"(lo), "f"(hi));
    asm("fma.rn.f32x2 %0, %1, %2, %0;" : "+l"(acc) : "l"(r), "l"(w));
}

#define UNPACK2(l, h, v) \
    asm("mov.b64 {%0, %1}, %2;" : "=f"(l), "=f"(h) : "l"(v))

// ---------------------------------------------------------------------------
// Kernel 0: presplit — 4 floats per thread.
// ---------------------------------------------------------------------------
__global__ __launch_bounds__(256)
void presplit_kernel(const float* __restrict__ enc, const float* __restrict__ dh,
                     const float* __restrict__ lo,  const float* __restrict__ We,
                     const float* __restrict__ Wt,  const float* __restrict__ Wl)
{
    const int z   = blockIdx.z;
    const int idx = blockIdx.x * 256 + threadIdx.x;
    if (z < 6) {
        const float* X; uint2* Y; int count4;
        switch (z) {
            case 0: X = enc; Y = g_encA; count4 = P_PIX  * E_DIM / 4; break;
            case 1: X = dh;  Y = g_dhA;  count4 = N_ROWS * E_DIM / 4; break;
            case 2: X = lo;  Y = g_loA;  count4 = N_ROWS * E_DIM / 4; break;
            case 3: X = We;  Y = g_WeP;  count4 = A_DIM  * E_DIM / 4; break;
            case 4: X = Wt;  Y = g_WtP;  count4 = A_DIM  * E_DIM / 4; break;
            default:X = Wl;  Y = g_WlP;  count4 = A_DIM  * E_DIM / 4; break;
        }
        if (idx < count4) {
            float4 v = *(const float4*)&X[4 * idx];
            uint2 u0 = split2(v.x, v.y);
            uint2 u1 = split2(v.z, v.w);
            uint4 pk; pk.x = u0.x; pk.y = u0.y; pk.z = u1.x; pk.w = u1.y;
            *(uint4*)&Y[2 * idx] = pk;
        }
    } else {
        if (idx < (P_PIX / 2) * (E_DIM / 2)) {
            int p2 = idx / (E_DIM / 2);
            int ec = (idx % (E_DIM / 2)) * 2;
            float2 r0 = *(const float2*)&enc[(2 * p2) * E_DIM + ec];
            float2 r1 = *(const float2*)&enc[(2 * p2 + 1) * E_DIM + ec];
            uint2 u0 = split2(r0.x, r1.x);
            uint2 u1 = split2(r0.y, r1.y);
            uint4 pk; pk.x = u0.x; pk.y = u0.y; pk.z = u1.x; pk.w = u1.y;
            *(uint4*)&g_encB[p2 * E_DIM + ec] = pk;
        }
    }
}

// ---------------------------------------------------------------------------
// Kernel 1: tc_attproj — C = A @ W^T + bias (M=1024, N=256, K=512), per z.
// CTA tile 64m x 32n, 128 threads, bf16 3-split k16 mma (proven).
// ---------------------------------------------------------------------------
__global__ __launch_bounds__(128)
void tc_attproj(const float* __restrict__ be, const float* __restrict__ bt,
                const float* __restrict__ bl)
{
    __shared__ uint2 Apk[2][64][SPAD];
    __shared__ uint2 Bpk[2][32][SPAD];

    const int z = blockIdx.z;
    const uint2* Asrc = (z == 0) ? g_encA : (z == 1) ? g_dhA : g_loA;
    const uint2* Bsrc = (z == 0) ? g_WeP  : (z == 1) ? g_WtP : g_WlP;
    const float* bv   = (z == 0) ? be     : (z == 1) ? bt    : bl;
    float*       C    = (z == 0) ? g_att1 : (z == 1) ? g_att23 : g_att3;

    const int tid = threadIdx.x;
    const int m0  = blockIdx.y * 64;
    const int n0  = blockIdx.x * 32;

    const int lane = tid & 31, wid = tid >> 5;
    const int wm = (wid & 1) * 32;
    const int wn = (wid >> 1) * 16;
    const int g = lane >> 2, t = lane & 3;

    float acc[2][2][4] = {};

    const int KP_ROW = E_DIM / 2;

    #define STAGE_P(kt, b)                                                   \
    {                                                                        \
        int kpb = (kt) * 16;                                                 \
        _Pragma("unroll")                                                    \
        for (int j = 0; j < 4; j++) {                                        \
            int o = tid + 128 * j;                                           \
            int r = o >> 3, kpc = (o & 7) * 2;                               \
            cpa16(&Apk[b][r][kpc], Asrc + (m0 + r) * KP_ROW + kpb + kpc);    \
        }                                                                    \
        _Pragma("unroll")                                                    \
        for (int j = 0; j < 2; j++) {                                        \
            int o = tid + 128 * j;                                           \
            int r = o >> 3, kpc = (o & 7) * 2;                               \
            cpa16(&Bpk[b][r][kpc], Bsrc + (n0 + r) * KP_ROW + kpb + kpc);    \
        }                                                                    \
        CP_COMMIT;                                                           \
    }

    STAGE_P(0, 0);
    const int T = E_DIM / 32;
    for (int it = 0; it < T; it++) {
        const int b = it & 1;
        if (it + 1 < T) { STAGE_P(it + 1, (it + 1) & 1); CP_WAIT(1); }
        else           { CP_WAIT(0); }
        __syncthreads();

        #pragma unroll
        for (int ks = 0; ks < 2; ks++) {
            const int kp0 = ks * 8;
            uint32_t Ah[2][4], Al[2][4];
            #pragma unroll
            for (int mf = 0; mf < 2; mf++) {
                int r = wm + mf * 16 + g;
                uint2 p00 = Apk[b][r][kp0 + t];
                uint2 p10 = Apk[b][r + 8][kp0 + t];
                uint2 p01 = Apk[b][r][kp0 + t + 4];
                uint2 p11 = Apk[b][r + 8][kp0 + t + 4];
                Ah[mf][0] = p00.x; Ah[mf][1] = p10.x; Ah[mf][2] = p01.x; Ah[mf][3] = p11.x;
                Al[mf][0] = p00.y; Al[mf][1] = p10.y; Al[mf][2] = p01.y; Al[mf][3] = p11.y;
            }
            uint32_t Bh[2][2], Bl[2][2];
            #pragma unroll
            for (int nf = 0; nf < 2; nf++) {
                int c = wn + nf * 8 + g;
                uint2 q0 = Bpk[b][c][kp0 + t];
                uint2 q1 = Bpk[b][c][kp0 + t + 4];
                Bh[nf][0] = q0.x; Bh[nf][1] = q1.x;
                Bl[nf][0] = q0.y; Bl[nf][1] = q1.y;
            }
            #pragma unroll
            for (int mf = 0; mf < 2; mf++)
                #pragma unroll
                for (int nf = 0; nf < 2; nf++) {
                    MMA_BF16(acc[mf][nf], Ah[mf], Bh[nf]);
                    MMA_BF16(acc[mf][nf], Ah[mf], Bl[nf]);
                    MMA_BF16(acc[mf][nf], Al[mf], Bh[nf]);
                }
        }
        __syncthreads();
    }
    #undef STAGE_P

    #pragma unroll
    for (int mf = 0; mf < 2; mf++)
        #pragma unroll
        for (int nf = 0; nf < 2; nf++) {
            int r = m0 + wm + mf * 16 + g;
            int c = n0 + wn + nf * 8 + t * 2;
            float b0 = bv[c], b1 = bv[c + 1];
            *(float2*)&C[r * A_DIM + c] =
                make_float2(acc[mf][nf][0] + b0, acc[mf][nf][1] + b1);
            *(float2*)&C[(r + 8) * A_DIM + c] =
                make_float2(acc[mf][nf][2] + b0, acc[mf][nf][3] + b1);
        }
}

// ---------------------------------------------------------------------------
// Kernel 2: att_main v5 — packed f32x2, relu on halves in C++ (mov-free goal).
// att[n,p] = sum_a relu(att1[p,a] + att23[n,a] + att3[n,a]) * Wf[a]
// 64n x 64p tile, 256 threads.
// ---------------------------------------------------------------------------
__global__ __launch_bounds__(256)
void att_main_v5(const float* __restrict__ Wf)
{
    __shared__ float s1  [32][68];    // [a][p]
    __shared__ float s23d[32][132];   // [a][2n] duplicated {v,v}
    __shared__ float swd [2 * A_DIM]; // Wf duplicated

    const int tid = threadIdx.x;
    const int tx  = tid & 15;         // p-group (4 p = 2 pairs)
    const int ty  = tid >> 4;         // n-group (4 n)
    const int p0  = blockIdx.x * 64;
    const int n0  = blockIdx.y * 64;

    {
        float w = Wf[tid];            // 256 threads == A_DIM
        *(float2*)&swd[2 * tid] = make_float2(w, w);
    }

    ull acc[4][2] = {};               // [n j][p-pair]

    for (int a0 = 0; a0 < A_DIM; a0 += 32) {
        __syncthreads();
        #pragma unroll
        for (int i = 0; i < 8; i++) {
            int e = tid + 256 * i;
            int a = e & 31, r = e >> 5;     // a 0..31, r 0..63
            s1[a][r] = g_att1[(p0 + r) * A_DIM + a0 + a];
            float v  = g_att23[(n0 + r) * A_DIM + a0 + a]
                     + g_att3 [(n0 + r) * A_DIM + a0 + a];
            *(float2*)&s23d[a][2 * r] = make_float2(v, v);
        }
        __syncthreads();

        #pragma unroll 4
        for (int a = 0; a < 32; a++) {
            ulonglong2 x1  = *(const ulonglong2*)&s1  [a][tx * 4];
            ulonglong2 x2a = *(const ulonglong2*)&s23d[a][ty * 8];
            ulonglong2 x2b = *(const ulonglong2*)&s23d[a][ty * 8 + 4];
            ull w = *(const ull*)&swd[2 * (a0 + a)];
            relu_fma2(acc[0][0], x1.x, x2a.x, w); relu_fma2(acc[0][1], x1.y, x2a.x, w);
            relu_fma2(acc[1][0], x1.x, x2a.y, w); relu_fma2(acc[1][1], x1.y, x2a.y, w);
            relu_fma2(acc[2][0], x1.x, x2b.x, w); relu_fma2(acc[2][1], x1.y, x2b.x, w);
            relu_fma2(acc[3][0], x1.x, x2b.y, w); relu_fma2(acc[3][1], x1.y, x2b.y, w);
        }
    }

    #pragma unroll
    for (int j = 0; j < 4; j++) {
        float l0, h0, l1, h1;
        UNPACK2(l0, h0, acc[j][0]);
        UNPACK2(l1, h1, acc[j][1]);
        *(float4*)&g_att[(n0 + ty * 4 + j) * P_PIX + p0 + tx * 4] =
            make_float4(l0, h0, l1, h1);
    }
}

// ---------------------------------------------------------------------------
// Kernel 3: softmax v3 — 1 warp/row, 4 rows per 128-thread block, grid 256.
// ---------------------------------------------------------------------------
__global__ __launch_bounds__(128)
void softmax_v3(float* __restrict__ alpha)
{
    const int tid  = threadIdx.x;
    const int lane = tid & 31;
    const int w    = tid >> 5;
    const int n    = blockIdx.x * 4 + w;

    const float4* row = (const float4*)(g_att + n * P_PIX);

    float4 v[8];
    #pragma unroll
    for (int j = 0; j < 8; j++) v[j] = row[lane + 32 * j];

    float m = -1e30f;
    #pragma unroll
    for (int j = 0; j < 8; j++)
        m = fmaxf(m, fmaxf(fmaxf(v[j].x, v[j].y), fmaxf(v[j].z, v[j].w)));
    #pragma unroll
    for (int o = 16; o > 0; o >>= 1) m = fmaxf(m, __shfl_xor_sync(0xffffffffu, m, o));

    float s = 0.0f;
    #pragma unroll
    for (int j = 0; j < 8; j++) {
        v[j].x = __expf(v[j].x - m); s += v[j].x;
        v[j].y = __expf(v[j].y - m); s += v[j].y;
        v[j].z = __expf(v[j].z - m); s += v[j].z;
        v[j].w = __expf(v[j].w - m); s += v[j].w;
    }
    #pragma unroll
    for (int o = 16; o > 0; o >>= 1) s += __shfl_xor_sync(0xffffffffu, s, o);
    const float inv = 1.0f / s;

    float4* arow = (float4*)(alpha + n * P_PIX);
    uint4*  prow = (uint4*)(g_alphaP + n * (P_PIX / 2));
    #pragma unroll
    for (int j = 0; j < 8; j++) {
        float a0 = v[j].x * inv, a1 = v[j].y * inv;
        float a2 = v[j].z * inv, a3 = v[j].w * inv;
        arow[lane + 32 * j] = make_float4(a0, a1, a2, a3);
        uint2 u0 = split2(a0, a1);
        uint2 u1 = split2(a2, a3);
        uint4 pk; pk.x = u0.x; pk.y = u0.y; pk.z = u1.x; pk.w = u1.y;
        prow[lane + 32 * j] = pk;
    }
}

// ---------------------------------------------------------------------------
// Kernel 4: tc_gemm_ab — awe = alpha @ enc  (M=1024, N=512, K=1024)
// CTA tile 64m x 32n, 128 threads, bf16 3-split (proven).
// ---------------------------------------------------------------------------
__global__ __launch_bounds__(128)
void tc_gemm_ab(float* __restrict__ C)
{
    __shared__ uint2 Apk[2][64][SPAD];
    __shared__ uint2 Bpk[2][16][36];

    const int tid = threadIdx.x;
    const int m0  = blockIdx.y * 64;
    const int n0  = blockIdx.x * 32;

    const int lane = tid & 31, wid = tid >> 5;
    const int wm = (wid & 1) * 32;
    const int wn = (wid >> 1) * 16;
    const int g = lane >> 2, t = lane & 3;

    float acc[2][2][4] = {};

    #define STAGE_G(kt, b)                                                    \
    {                                                                         \
        int kpb = (kt) * 16;                                                  \
        _Pragma("unroll")                                                     \
        for (int j = 0; j < 4; j++) {                                         \
            int o = tid + 128 * j;                                            \
            int r = o >> 3, kpc = (o & 7) * 2;                                \
            cpa16(&Apk[b][r][kpc],                                            \
                  g_alphaP + (m0 + r) * (P_PIX / 2) + kpb + kpc);             \
        }                                                                     \
        _Pragma("unroll")                                                     \
        for (int j = 0; j < 2; j++) {                                         \
            int o = tid + 128 * j;                                            \
            int kp = o >> 4, nc = (o & 15) * 2;                               \
            cpa16(&Bpk[b][kp][nc], g_encB + (kpb + kp) * E_DIM + n0 + nc);    \
        }                                                                     \
        CP_COMMIT;                                                            \
    }

    STAGE_G(0, 0);
    const int T = P_PIX / 32;
    for (int it = 0; it < T; it++) {
        const int b = it & 1;
        if (it + 1 < T) { STAGE_G(it + 1, (it + 1) & 1); CP_WAIT(1); }
        else           { CP_WAIT(0); }
        __syncthreads();

        #pragma unroll
        for (int ks = 0; ks < 2; ks++) {
            const int kp0 = ks * 8;
            uint32_t Ah[2][4], Al[2][4];
            #pragma unroll
            for (int mf = 0; mf < 2; mf++) {
                int r = wm + mf * 16 + g;
                uint2 p00 = Apk[b][r][kp0 + t];
                uint2 p10 = Apk[b][r + 8][kp0 + t];
                uint2 p01 = Apk[b][r][kp0 + t + 4];
                uint2 p11 = Apk[b][r + 8][kp0 + t + 4];
                Ah[mf][0] = p00.x; Ah[mf][1] = p10.x; Ah[mf][2] = p01.x; Ah[mf][3] = p11.x;
                Al[mf][0] = p00.y; Al[mf][1] = p10.y; Al[mf][2] = p01.y; Al[mf][3] = p11.y;
            }
            uint32_t Bh[2][2], Bl[2][2];
            #pragma unroll
            for (int nf = 0; nf < 2; nf++) {
                int c = wn + nf * 8 + g;
                uint2 q0 = Bpk[b][kp0 + t][c];
                uint2 q1 = Bpk[b][kp0 + t + 4][c];
                Bh[nf][0] = q0.x; Bh[nf][1] = q1.x;
                Bl[nf][0] = q0.y; Bl[nf][1] = q1.y;
            }
            #pragma unroll
            for (int mf = 0; mf < 2; mf++)
                #pragma unroll
                for (int nf = 0; nf < 2; nf++) {
                    MMA_BF16(acc[mf][nf], Ah[mf], Bh[nf]);
                    MMA_BF16(acc[mf][nf], Ah[mf], Bl[nf]);
                    MMA_BF16(acc[mf][nf], Al[mf], Bh[nf]);
                }
        }
        __syncthreads();
    }
    #undef STAGE_G

    #pragma unroll
    for (int mf = 0; mf < 2; mf++)
        #pragma unroll
        for (int nf = 0; nf < 2; nf++) {
            int r = m0 + wm + mf * 16 + g;
            int c = n0 + wn + nf * 8 + t * 2;
            *(float2*)&C[r * E_DIM + c] =
                make_float2(acc[mf][nf][0], acc[mf][nf][1]);
            *(float2*)&C[(r + 8) * E_DIM + c] =
                make_float2(acc[mf][nf][2], acc[mf][nf][3]);
        }
}

// ---------------------------------------------------------------------------
// Launch
// ---------------------------------------------------------------------------
extern "C" void kernel_launch(void* const* d_in, const int* in_sizes, int n_in,
                              void* d_out, int out_size)
{
    (void)in_sizes; (void)n_in; (void)out_size;
    const float* enc = (const float*)d_in[0];
    const float* dh  = (const float*)d_in[1];
    const float* lo  = (const float*)d_in[2];
    const float* We  = (const float*)d_in[3];
    const float* be  = (const float*)d_in[4];
    const float* Wt  = (const float*)d_in[5];
    const float* bt  = (const float*)d_in[6];
    const float* Wl  = (const float*)d_in[7];
    const float* bl  = (const float*)d_in[8];
    const float* Wf  = (const float*)d_in[9];
    // d_in[10] = bf: uniform shift, cancels in softmax.

    float* awe   = (float*)d_out;
    float* alpha = (float*)d_out + N_ROWS * E_DIM;

    dim3 g0(512, 1, 7);
    presplit_kernel<<<g0, 256>>>(enc, dh, lo, We, Wt, Wl);

    dim3 g1(A_DIM / 32, 1024 / 64, 3);
    tc_attproj<<<g1, 128>>>(be, bt, bl);

    dim3 g2(P_PIX / 64, N_ROWS / 64);
    att_main_v5<<<g2, 256>>>(Wf);

    softmax_v3<<<N_ROWS / 4, 128>>>(alpha);

    dim3 g4(E_DIM / 32, N_ROWS / 64);
    tc_gemm_ab<<<g4, 128>>>(awe);
}